// round 1
// baseline (speedup 1.0000x reference)
#include <cuda_runtime.h>
#include <cstdint>

#define NN 50000
#define NE 500000
#define DD 128

// Scratch (static __device__ arrays: the allowed scratch mechanism)
__device__ float g_Y[(size_t)NN * 1024];    // Y[n][k*128+o] = sum_i x[n,i] W1[i,k,o]      (i in [0,128))
__device__ float g_Z[(size_t)NN * 1024];    // Z[n][k*128+o] = sum_i x[n,i] W1[128+i,k,o]
__device__ float g_agg[(size_t)NN * DD];    // scatter-add aggregation

__device__ __forceinline__ float swishf(float v) {
    return __fdividef(v, 1.0f + __expf(-v));
}

__global__ void k_zero_agg() {
    int i = blockIdx.x * blockDim.x + threadIdx.x;
    const int n = NN * DD;
    for (; i < n; i += gridDim.x * blockDim.x) g_agg[i] = 0.0f;
}

// ---------------------------------------------------------------------------
// Precompute Y and Z:  [50000 x 128] @ [128 x 1024]  (two halves of W1)
// grid: (391 node tiles, 8 col tiles, 2 halves), 256 threads, 128x128 C tile
// ---------------------------------------------------------------------------
__global__ void __launch_bounds__(256) k_precompute(const float* __restrict__ x,
                                                    const float* __restrict__ W1) {
    __shared__ float As[8][132];
    __shared__ float Bs[8][128];
    const int n0 = blockIdx.x * 128;
    const int c0 = blockIdx.y * 128;
    const float* B = W1 + (size_t)blockIdx.z * 128 * 1024 + c0;
    float* C = (blockIdx.z == 0) ? g_Y : g_Z;
    const int tid = threadIdx.x;
    const int tx = tid & 15, ty = tid >> 4;
    const int lr = tid >> 1, lc4 = (tid & 1) * 4;
    const int br = tid >> 5, bc4 = (tid & 31) * 4;
    int gn_l = n0 + lr; if (gn_l >= NN) gn_l = NN - 1;

    float acc[8][8];
#pragma unroll
    for (int m = 0; m < 8; m++)
#pragma unroll
        for (int n = 0; n < 8; n++) acc[m][n] = 0.0f;

    for (int i0 = 0; i0 < 128; i0 += 8) {
        float4 av = *(const float4*)(x + (size_t)gn_l * 128 + i0 + lc4);
        As[lc4 + 0][lr] = av.x;
        As[lc4 + 1][lr] = av.y;
        As[lc4 + 2][lr] = av.z;
        As[lc4 + 3][lr] = av.w;
        *(float4*)&Bs[br][bc4] = *(const float4*)(B + (size_t)(i0 + br) * 1024 + bc4);
        __syncthreads();
#pragma unroll
        for (int kk = 0; kk < 8; kk++) {
            float4 a0 = *(const float4*)&As[kk][ty * 4];
            float4 a1 = *(const float4*)&As[kk][64 + ty * 4];
            float4 b0 = *(const float4*)&Bs[kk][tx * 4];
            float4 b1 = *(const float4*)&Bs[kk][64 + tx * 4];
            float a[8] = {a0.x, a0.y, a0.z, a0.w, a1.x, a1.y, a1.z, a1.w};
            float b[8] = {b0.x, b0.y, b0.z, b0.w, b1.x, b1.y, b1.z, b1.w};
#pragma unroll
            for (int m = 0; m < 8; m++)
#pragma unroll
                for (int n = 0; n < 8; n++) acc[m][n] = fmaf(a[m], b[n], acc[m][n]);
        }
        __syncthreads();
    }
#pragma unroll
    for (int m = 0; m < 8; m++) {
        const int row = (m < 4) ? (ty * 4 + m) : (64 + ty * 4 + m - 4);
        const int gn = n0 + row;
        if (gn >= NN) continue;
        float* cp = C + (size_t)gn * 1024 + c0;
        float4 v0 = {acc[m][0], acc[m][1], acc[m][2], acc[m][3]};
        float4 v1 = {acc[m][4], acc[m][5], acc[m][6], acc[m][7]};
        *(float4*)(cp + tx * 4) = v0;
        *(float4*)(cp + 64 + tx * 4) = v1;
    }
}

// ---------------------------------------------------------------------------
// Edge kernel: 128 edges per CTA, 256 threads.
// phase1: m1 = swish(b1 + sum_k ea_k*(Y[dst]+Z[src]) + amf-term)  -> smem (transposed)
// phase2: C = sum_{k,i} (m1[e,i]*ea[e,k]) * W2[i,k,o]   (K=1024 sgemm)
// phase3: atomicAdd(agg[dst], swish(C + b2))
// ---------------------------------------------------------------------------
__global__ void __launch_bounds__(256, 1) k_edges(
    const int* __restrict__ eidx, const float* __restrict__ ea,
    const float* __restrict__ amf, const float* __restrict__ W1,
    const float* __restrict__ b1, const float* __restrict__ W2,
    const float* __restrict__ b2) {
    extern __shared__ float sm[];
    float* s_ea  = sm;            // 1024 floats: [128 edges][8]
    float* s_w1c = sm + 1024;     // 3072: W1 rows 256..258  [i][k][o]
    float* s_m1T = sm + 4096;     // 128*132: m1 transposed [i][e]
    float* s_Bs  = sm + 20992;    // 8*128 W2 tile
    const int tid = threadIdx.x;
    const int e0 = blockIdx.x * 128;

    for (int i = tid; i < 1024; i += 256) {
        const int idx = e0 * 8 + i;
        s_ea[i] = (idx < NE * 8) ? ea[idx] : 0.0f;
    }
    for (int i = tid; i < 3072; i += 256) s_w1c[i] = W1[256 * 1024 + i];
    __syncthreads();

    // ----- phase 1: 2 threads per edge, 64 outputs each -----
    {
        const int e = tid >> 1;
        const int oh = (tid & 1) * 64;
        const int ge = e0 + e;
        const bool valid = ge < NE;
        const int gsrc = valid ? eidx[ge] : 0;
        const int gdst = valid ? eidx[NE + ge] : 0;
        const float am0 = valid ? amf[ge * 3 + 0] : 0.0f;
        const float am1 = valid ? amf[ge * 3 + 1] : 0.0f;
        const float am2 = valid ? amf[ge * 3 + 2] : 0.0f;
        float acc[64];
#pragma unroll
        for (int j = 0; j < 64; j += 4) {
            float4 bv = *(const float4*)(b1 + oh + j);
            acc[j] = bv.x; acc[j + 1] = bv.y; acc[j + 2] = bv.z; acc[j + 3] = bv.w;
        }
        const float* Yb = g_Y + (size_t)gdst * 1024 + oh;
        const float* Zb = g_Z + (size_t)gsrc * 1024 + oh;
#pragma unroll 1
        for (int k = 0; k < 8; k++) {
            const float eak = s_ea[e * 8 + k];
            const float4* y4 = (const float4*)(Yb + k * 128);
            const float4* z4 = (const float4*)(Zb + k * 128);
            const float4* wA = (const float4*)(s_w1c + k * 128 + oh);
            const float4* wB = (const float4*)(s_w1c + 1024 + k * 128 + oh);
            const float4* wC = (const float4*)(s_w1c + 2048 + k * 128 + oh);
#pragma unroll
            for (int j = 0; j < 16; j++) {
                float4 t = y4[j];
                float4 z = z4[j];
                float4 wa = wA[j], wb = wB[j], wc = wC[j];
                float vx = t.x + z.x, vy = t.y + z.y, vz = t.z + z.z, vw = t.w + z.w;
                vx = fmaf(am0, wa.x, vx); vy = fmaf(am0, wa.y, vy);
                vz = fmaf(am0, wa.z, vz); vw = fmaf(am0, wa.w, vw);
                vx = fmaf(am1, wb.x, vx); vy = fmaf(am1, wb.y, vy);
                vz = fmaf(am1, wb.z, vz); vw = fmaf(am1, wb.w, vw);
                vx = fmaf(am2, wc.x, vx); vy = fmaf(am2, wc.y, vy);
                vz = fmaf(am2, wc.z, vz); vw = fmaf(am2, wc.w, vw);
                acc[4 * j + 0] = fmaf(eak, vx, acc[4 * j + 0]);
                acc[4 * j + 1] = fmaf(eak, vy, acc[4 * j + 1]);
                acc[4 * j + 2] = fmaf(eak, vz, acc[4 * j + 2]);
                acc[4 * j + 3] = fmaf(eak, vw, acc[4 * j + 3]);
            }
        }
#pragma unroll
        for (int j = 0; j < 64; j++)
            s_m1T[(oh + j) * 132 + e] = swishf(acc[j]);
    }
    __syncthreads();

    // ----- phase 2: 128x128 C tile, K = 8k * 128i -----
    const int tx = tid & 15, ty = tid >> 4;
    const int bi = tid >> 5, bo4 = (tid & 31) * 4;
    float c[8][8];
#pragma unroll
    for (int m = 0; m < 8; m++)
#pragma unroll
        for (int n = 0; n < 8; n++) c[m][n] = 0.0f;

    for (int k = 0; k < 8; k++) {
        float eas[8];
#pragma unroll
        for (int m = 0; m < 8; m++) {
            const int row = (m < 4) ? (ty * 4 + m) : (64 + ty * 4 + m - 4);
            eas[m] = s_ea[row * 8 + k];
        }
        for (int i0 = 0; i0 < 128; i0 += 8) {
            __syncthreads();
            *(float4*)&s_Bs[bi * 128 + bo4] =
                *(const float4*)(W2 + ((size_t)(i0 + bi) * 8 + k) * 128 + bo4);
            __syncthreads();
#pragma unroll
            for (int kk = 0; kk < 8; kk++) {
                const float* ar = s_m1T + (i0 + kk) * 132;
                float4 a0 = *(const float4*)(ar + ty * 4);
                float4 a1 = *(const float4*)(ar + 64 + ty * 4);
                float4 b0 = *(const float4*)(s_Bs + kk * 128 + tx * 4);
                float4 b1v = *(const float4*)(s_Bs + kk * 128 + 64 + tx * 4);
                float a[8] = {a0.x * eas[0], a0.y * eas[1], a0.z * eas[2], a0.w * eas[3],
                              a1.x * eas[4], a1.y * eas[5], a1.z * eas[6], a1.w * eas[7]};
                float b[8] = {b0.x, b0.y, b0.z, b0.w, b1v.x, b1v.y, b1v.z, b1v.w};
#pragma unroll
                for (int m = 0; m < 8; m++)
#pragma unroll
                    for (int n = 0; n < 8; n++) c[m][n] = fmaf(a[m], b[n], c[m][n]);
            }
        }
    }

    // ----- phase 3: swish + scatter-add -----
    float4 b2lo = *(const float4*)(b2 + tx * 4);
    float4 b2hi = *(const float4*)(b2 + 64 + tx * 4);
    const float bb[8] = {b2lo.x, b2lo.y, b2lo.z, b2lo.w, b2hi.x, b2hi.y, b2hi.z, b2hi.w};
#pragma unroll
    for (int m = 0; m < 8; m++) {
        const int row = (m < 4) ? (ty * 4 + m) : (64 + ty * 4 + m - 4);
        const int ge = e0 + row;
        if (ge >= NE) continue;
        const int gd = eidx[NE + ge];
        float* ap = g_agg + (size_t)gd * 128;
#pragma unroll
        for (int n = 0; n < 8; n++) {
            const int col = (n < 4) ? (tx * 4 + n) : (64 + tx * 4 + n - 4);
            atomicAdd(ap + col, swishf(c[m][n] + bb[n]));
        }
    }
}

// ---------------------------------------------------------------------------
// Node kernel: 128 nodes per CTA. Layer3 (K = 259*8) then Layer4 (K = 128*8).
// ---------------------------------------------------------------------------
__global__ void __launch_bounds__(256, 1) k_nodes(
    const float* __restrict__ x, const float* __restrict__ na,
    const float* __restrict__ anf,
    const float* __restrict__ W3, const float* __restrict__ b3,
    const float* __restrict__ W4, const float* __restrict__ b4,
    float* __restrict__ out) {
    extern __shared__ float sm[];
    float* s_na   = sm;            // 1024
    float* s_anfT = sm + 1024;     // 8*132 (rows 3..7 zero)
    float* s_xT   = sm + 2080;     // 128*132   (reused as uT for layer 4)
    float* s_gT   = sm + 18976;    // 128*132
    float* s_Bs   = sm + 35872;    // 1024
    const int tid = threadIdx.x;
    const int n0 = blockIdx.x * 128;
    const int tx = tid & 15, ty = tid >> 4;
    const int bi = tid >> 5, bo4 = (tid & 31) * 4;

    for (int i = tid; i < 1024; i += 256) {
        const int idx = n0 * 8 + i;
        s_na[i] = (idx < NN * 8) ? na[idx] : 0.0f;
    }
    {
        const int r = tid >> 1;
        const int off = (tid & 1) * 64;
        int gn = n0 + r; if (gn >= NN) gn = NN - 1;
#pragma unroll
        for (int j = 0; j < 64; j += 4) {
            float4 v = *(const float4*)(x + (size_t)gn * 128 + off + j);
            s_xT[(off + j + 0) * 132 + r] = v.x;
            s_xT[(off + j + 1) * 132 + r] = v.y;
            s_xT[(off + j + 2) * 132 + r] = v.z;
            s_xT[(off + j + 3) * 132 + r] = v.w;
            float4 g = *(const float4*)(g_agg + (size_t)gn * 128 + off + j);
            s_gT[(off + j + 0) * 132 + r] = g.x;
            s_gT[(off + j + 1) * 132 + r] = g.y;
            s_gT[(off + j + 2) * 132 + r] = g.z;
            s_gT[(off + j + 3) * 132 + r] = g.w;
        }
    }
    if (tid < 128) {
        int gn = n0 + tid;
        const bool v = gn < NN;
        if (!v) gn = 0;
#pragma unroll
        for (int i = 0; i < 8; i++)
            s_anfT[i * 132 + tid] = (i < 3 && v) ? anf[gn * 3 + i] : 0.0f;
    }
    __syncthreads();

    float c[8][8];
#pragma unroll
    for (int m = 0; m < 8; m++)
#pragma unroll
        for (int n = 0; n < 8; n++) c[m][n] = 0.0f;

    // ----- layer 3: K = 259*8 -----
    for (int k = 0; k < 8; k++) {
        float nas[8];
#pragma unroll
        for (int m = 0; m < 8; m++) {
            const int row = (m < 4) ? (ty * 4 + m) : (64 + ty * 4 + m - 4);
            nas[m] = s_na[row * 8 + k];
        }
        for (int blk = 0; blk < 33; blk++) {
            const float* AT = (blk < 16) ? (s_xT + blk * 8 * 132)
                            : (blk < 32) ? (s_gT + (blk - 16) * 8 * 132)
                                         : s_anfT;
            const int gi = blk * 8 + bi;
            __syncthreads();
            float4 bv = make_float4(0.f, 0.f, 0.f, 0.f);
            if (gi < 259)
                bv = *(const float4*)(W3 + ((size_t)gi * 8 + k) * 128 + bo4);
            *(float4*)&s_Bs[bi * 128 + bo4] = bv;
            __syncthreads();
#pragma unroll
            for (int kk = 0; kk < 8; kk++) {
                const float* ar = AT + kk * 132;
                float4 a0 = *(const float4*)(ar + ty * 4);
                float4 a1 = *(const float4*)(ar + 64 + ty * 4);
                float4 b0 = *(const float4*)(s_Bs + kk * 128 + tx * 4);
                float4 b1v = *(const float4*)(s_Bs + kk * 128 + 64 + tx * 4);
                float a[8] = {a0.x * nas[0], a0.y * nas[1], a0.z * nas[2], a0.w * nas[3],
                              a1.x * nas[4], a1.y * nas[5], a1.z * nas[6], a1.w * nas[7]};
                float b[8] = {b0.x, b0.y, b0.z, b0.w, b1v.x, b1v.y, b1v.z, b1v.w};
#pragma unroll
                for (int m = 0; m < 8; m++)
#pragma unroll
                    for (int n = 0; n < 8; n++) c[m][n] = fmaf(a[m], b[n], c[m][n]);
            }
        }
    }

    // u = swish(c + b3) -> uT (overwrite s_xT; all layer-3 reads are done)
    __syncthreads();
    {
        float4 b3lo = *(const float4*)(b3 + tx * 4);
        float4 b3hi = *(const float4*)(b3 + 64 + tx * 4);
        const float bb[8] = {b3lo.x, b3lo.y, b3lo.z, b3lo.w, b3hi.x, b3hi.y, b3hi.z, b3hi.w};
#pragma unroll
        for (int m = 0; m < 8; m++) {
            const int row = (m < 4) ? (ty * 4 + m) : (64 + ty * 4 + m - 4);
#pragma unroll
            for (int n = 0; n < 8; n++) {
                const int col = (n < 4) ? (tx * 4 + n) : (64 + tx * 4 + n - 4);
                s_xT[col * 132 + row] = swishf(c[m][n] + bb[n]);
            }
        }
    }
    __syncthreads();

    // ----- layer 4: K = 128*8 -----
#pragma unroll
    for (int m = 0; m < 8; m++)
#pragma unroll
        for (int n = 0; n < 8; n++) c[m][n] = 0.0f;

    for (int k = 0; k < 8; k++) {
        float nas[8];
#pragma unroll
        for (int m = 0; m < 8; m++) {
            const int row = (m < 4) ? (ty * 4 + m) : (64 + ty * 4 + m - 4);
            nas[m] = s_na[row * 8 + k];
        }
        for (int i0 = 0; i0 < 128; i0 += 8) {
            __syncthreads();
            *(float4*)&s_Bs[bi * 128 + bo4] =
                *(const float4*)(W4 + ((size_t)(i0 + bi) * 8 + k) * 128 + bo4);
            __syncthreads();
#pragma unroll
            for (int kk = 0; kk < 8; kk++) {
                const float* ar = s_xT + (i0 + kk) * 132;
                float4 a0 = *(const float4*)(ar + ty * 4);
                float4 a1 = *(const float4*)(ar + 64 + ty * 4);
                float4 b0 = *(const float4*)(s_Bs + kk * 128 + tx * 4);
                float4 b1v = *(const float4*)(s_Bs + kk * 128 + 64 + tx * 4);
                float a[8] = {a0.x * nas[0], a0.y * nas[1], a0.z * nas[2], a0.w * nas[3],
                              a1.x * nas[4], a1.y * nas[5], a1.z * nas[6], a1.w * nas[7]};
                float b[8] = {b0.x, b0.y, b0.z, b0.w, b1v.x, b1v.y, b1v.z, b1v.w};
#pragma unroll
                for (int m = 0; m < 8; m++)
#pragma unroll
                    for (int n = 0; n < 8; n++) c[m][n] = fmaf(a[m], b[n], c[m][n]);
            }
        }
    }

    // out = c + b4
    {
        float4 b4lo = *(const float4*)(b4 + tx * 4);
        float4 b4hi = *(const float4*)(b4 + 64 + tx * 4);
#pragma unroll
        for (int m = 0; m < 8; m++) {
            const int row = (m < 4) ? (ty * 4 + m) : (64 + ty * 4 + m - 4);
            const int gn = n0 + row;
            if (gn >= NN) continue;
            float4 v0 = {c[m][0] + b4lo.x, c[m][1] + b4lo.y, c[m][2] + b4lo.z, c[m][3] + b4lo.w};
            float4 v1 = {c[m][4] + b4hi.x, c[m][5] + b4hi.y, c[m][6] + b4hi.z, c[m][7] + b4hi.w};
            *(float4*)(out + (size_t)gn * 128 + tx * 4) = v0;
            *(float4*)(out + (size_t)gn * 128 + 64 + tx * 4) = v1;
        }
    }
}

extern "C" void kernel_launch(void* const* d_in, const int* in_sizes, int n_in,
                              void* d_out, int out_size) {
    const float *x = nullptr, *ea = nullptr, *na = nullptr, *amf = nullptr, *anf = nullptr;
    const float *W1 = nullptr, *b1 = nullptr, *W2 = nullptr, *b2 = nullptr;
    const float *W3 = nullptr, *b3 = nullptr, *W4 = nullptr, *b4 = nullptr;
    const int* eidx = nullptr;
    for (int i = 0; i < n_in; i++) {
        switch (in_sizes[i]) {
            case 6400000: x   = (const float*)d_in[i]; break;
            case 1000000: eidx = (const int*)d_in[i]; break;
            case 4000000: ea  = (const float*)d_in[i]; break;
            case 400000:  na  = (const float*)d_in[i]; break;
            case 1500000: amf = (const float*)d_in[i]; break;
            case 150000:  anf = (const float*)d_in[i]; break;
            case 265216:  if (!W1) W1 = (const float*)d_in[i]; else W3 = (const float*)d_in[i]; break;
            case 131072:  if (!W2) W2 = (const float*)d_in[i]; else W4 = (const float*)d_in[i]; break;
            case 128:
                if (!b1) b1 = (const float*)d_in[i];
                else if (!b2) b2 = (const float*)d_in[i];
                else if (!b3) b3 = (const float*)d_in[i];
                else b4 = (const float*)d_in[i];
                break;
            default: break;  // batch (50000 int64) unused
        }
    }

    cudaFuncSetAttribute(k_edges, cudaFuncAttributeMaxDynamicSharedMemorySize, 88064);
    cudaFuncSetAttribute(k_nodes, cudaFuncAttributeMaxDynamicSharedMemorySize, 147584);

    k_zero_agg<<<12500, 512>>>();
    dim3 gp(391, 8, 2);
    k_precompute<<<gp, 256>>>(x, W1);
    k_edges<<<3907, 256, 88064>>>(eidx, ea, amf, W1, b1, W2, b2);
    k_nodes<<<391, 256, 147584>>>(x, na, anf, W3, b3, W4, b4, (float*)d_out);
}

// round 2
// speedup vs baseline: 1.0086x; 1.0086x over previous
#include <cuda_runtime.h>
#include <cstdint>

#define NN 50000
#define NE 500000
#define DD 128

// Scratch (static __device__ arrays: the allowed scratch mechanism)
__device__ float g_Y[(size_t)NN * 1024];    // Y[n][k*128+o] = sum_i x[n,i] W1[i,k,o]      (i in [0,128))
__device__ float g_Z[(size_t)NN * 1024];    // Z[n][k*128+o] = sum_i x[n,i] W1[128+i,k,o]
__device__ float g_agg[(size_t)NN * DD];    // scatter-add aggregation

__device__ __forceinline__ float swishf(float v) {
    return __fdividef(v, 1.0f + __expf(-v));
}

__global__ void k_zero_agg() {
    int i = blockIdx.x * blockDim.x + threadIdx.x;
    const int n = NN * DD;
    for (; i < n; i += gridDim.x * blockDim.x) g_agg[i] = 0.0f;
}

// ---------------------------------------------------------------------------
// Precompute Y and Z:  [50000 x 128] @ [128 x 1024]  (two halves of W1)
// grid: (391 node tiles, 8 col tiles, 2 halves), 256 threads, 128x128 C tile
// ---------------------------------------------------------------------------
__global__ void __launch_bounds__(256) k_precompute(const float* __restrict__ x,
                                                    const float* __restrict__ W1) {
    __shared__ float As[8][132];
    __shared__ float Bs[8][128];
    const int n0 = blockIdx.x * 128;
    const int c0 = blockIdx.y * 128;
    const float* B = W1 + (size_t)blockIdx.z * 128 * 1024 + c0;
    float* C = (blockIdx.z == 0) ? g_Y : g_Z;
    const int tid = threadIdx.x;
    const int tx = tid & 15, ty = tid >> 4;
    const int lr = tid >> 1, lc4 = (tid & 1) * 4;
    const int br = tid >> 5, bc4 = (tid & 31) * 4;
    int gn_l = n0 + lr; if (gn_l >= NN) gn_l = NN - 1;

    float acc[8][8];
#pragma unroll
    for (int m = 0; m < 8; m++)
#pragma unroll
        for (int n = 0; n < 8; n++) acc[m][n] = 0.0f;

    for (int i0 = 0; i0 < 128; i0 += 8) {
        float4 av = *(const float4*)(x + (size_t)gn_l * 128 + i0 + lc4);
        As[lc4 + 0][lr] = av.x;
        As[lc4 + 1][lr] = av.y;
        As[lc4 + 2][lr] = av.z;
        As[lc4 + 3][lr] = av.w;
        *(float4*)&Bs[br][bc4] = *(const float4*)(B + (size_t)(i0 + br) * 1024 + bc4);
        __syncthreads();
#pragma unroll
        for (int kk = 0; kk < 8; kk++) {
            float4 a0 = *(const float4*)&As[kk][ty * 4];
            float4 a1 = *(const float4*)&As[kk][64 + ty * 4];
            float4 b0 = *(const float4*)&Bs[kk][tx * 4];
            float4 b1 = *(const float4*)&Bs[kk][64 + tx * 4];
            float a[8] = {a0.x, a0.y, a0.z, a0.w, a1.x, a1.y, a1.z, a1.w};
            float b[8] = {b0.x, b0.y, b0.z, b0.w, b1.x, b1.y, b1.z, b1.w};
#pragma unroll
            for (int m = 0; m < 8; m++)
#pragma unroll
                for (int n = 0; n < 8; n++) acc[m][n] = fmaf(a[m], b[n], acc[m][n]);
        }
        __syncthreads();
    }
#pragma unroll
    for (int m = 0; m < 8; m++) {
        const int row = (m < 4) ? (ty * 4 + m) : (64 + ty * 4 + m - 4);
        const int gn = n0 + row;
        if (gn >= NN) continue;
        float* cp = C + (size_t)gn * 1024 + c0;
        float4 v0 = {acc[m][0], acc[m][1], acc[m][2], acc[m][3]};
        float4 v1 = {acc[m][4], acc[m][5], acc[m][6], acc[m][7]};
        *(float4*)(cp + tx * 4) = v0;
        *(float4*)(cp + 64 + tx * 4) = v1;
    }
}

// ---------------------------------------------------------------------------
// Edge kernel: 128 edges per CTA, 256 threads.
// phase1: m1 = swish(b1 + sum_k ea_k*(Y[dst]+Z[src]) + amf-term)  -> smem (transposed)
// phase2: C = sum_{k,i} (m1[e,i]*ea[e,k]) * W2[i,k,o]   (K=1024 sgemm)
// phase3: atomicAdd(agg[dst], swish(C + b2))
// ---------------------------------------------------------------------------
__global__ void __launch_bounds__(256, 1) k_edges(
    const int* __restrict__ eidx, const float* __restrict__ ea,
    const float* __restrict__ amf, const float* __restrict__ W1,
    const float* __restrict__ b1, const float* __restrict__ W2,
    const float* __restrict__ b2) {
    extern __shared__ float sm[];
    float* s_ea  = sm;            // 1024 floats: [128 edges][8]
    float* s_w1c = sm + 1024;     // 3072: W1 rows 256..258  [i][k][o]
    float* s_m1T = sm + 4096;     // 128*132: m1 transposed [i][e]
    float* s_Bs  = sm + 20992;    // 8*128 W2 tile
    const int tid = threadIdx.x;
    const int e0 = blockIdx.x * 128;

    for (int i = tid; i < 1024; i += 256) {
        const int idx = e0 * 8 + i;
        s_ea[i] = (idx < NE * 8) ? ea[idx] : 0.0f;
    }
    for (int i = tid; i < 3072; i += 256) s_w1c[i] = W1[256 * 1024 + i];
    __syncthreads();

    // ----- phase 1: 2 threads per edge, 64 outputs each -----
    {
        const int e = tid >> 1;
        const int oh = (tid & 1) * 64;
        const int ge = e0 + e;
        const bool valid = ge < NE;
        const int gsrc = valid ? eidx[ge] : 0;
        const int gdst = valid ? eidx[NE + ge] : 0;
        const float am0 = valid ? amf[ge * 3 + 0] : 0.0f;
        const float am1 = valid ? amf[ge * 3 + 1] : 0.0f;
        const float am2 = valid ? amf[ge * 3 + 2] : 0.0f;
        float acc[64];
#pragma unroll
        for (int j = 0; j < 64; j += 4) {
            float4 bv = *(const float4*)(b1 + oh + j);
            acc[j] = bv.x; acc[j + 1] = bv.y; acc[j + 2] = bv.z; acc[j + 3] = bv.w;
        }
        const float* Yb = g_Y + (size_t)gdst * 1024 + oh;
        const float* Zb = g_Z + (size_t)gsrc * 1024 + oh;
#pragma unroll 1
        for (int k = 0; k < 8; k++) {
            const float eak = s_ea[e * 8 + k];
            const float4* y4 = (const float4*)(Yb + k * 128);
            const float4* z4 = (const float4*)(Zb + k * 128);
            const float4* wA = (const float4*)(s_w1c + k * 128 + oh);
            const float4* wB = (const float4*)(s_w1c + 1024 + k * 128 + oh);
            const float4* wC = (const float4*)(s_w1c + 2048 + k * 128 + oh);
#pragma unroll
            for (int j = 0; j < 16; j++) {
                float4 t = y4[j];
                float4 z = z4[j];
                float4 wa = wA[j], wb = wB[j], wc = wC[j];
                float vx = t.x + z.x, vy = t.y + z.y, vz = t.z + z.z, vw = t.w + z.w;
                vx = fmaf(am0, wa.x, vx); vy = fmaf(am0, wa.y, vy);
                vz = fmaf(am0, wa.z, vz); vw = fmaf(am0, wa.w, vw);
                vx = fmaf(am1, wb.x, vx); vy = fmaf(am1, wb.y, vy);
                vz = fmaf(am1, wb.z, vz); vw = fmaf(am1, wb.w, vw);
                vx = fmaf(am2, wc.x, vx); vy = fmaf(am2, wc.y, vy);
                vz = fmaf(am2, wc.z, vz); vw = fmaf(am2, wc.w, vw);
                acc[4 * j + 0] = fmaf(eak, vx, acc[4 * j + 0]);
                acc[4 * j + 1] = fmaf(eak, vy, acc[4 * j + 1]);
                acc[4 * j + 2] = fmaf(eak, vz, acc[4 * j + 2]);
                acc[4 * j + 3] = fmaf(eak, vw, acc[4 * j + 3]);
            }
        }
#pragma unroll
        for (int j = 0; j < 64; j++)
            s_m1T[(oh + j) * 132 + e] = swishf(acc[j]);
    }
    __syncthreads();

    // ----- phase 2: 128x128 C tile, K = 8k * 128i -----
    const int tx = tid & 15, ty = tid >> 4;
    const int bi = tid >> 5, bo4 = (tid & 31) * 4;
    float c[8][8];
#pragma unroll
    for (int m = 0; m < 8; m++)
#pragma unroll
        for (int n = 0; n < 8; n++) c[m][n] = 0.0f;

    for (int k = 0; k < 8; k++) {
        float eas[8];
#pragma unroll
        for (int m = 0; m < 8; m++) {
            const int row = (m < 4) ? (ty * 4 + m) : (64 + ty * 4 + m - 4);
            eas[m] = s_ea[row * 8 + k];
        }
        for (int i0 = 0; i0 < 128; i0 += 8) {
            __syncthreads();
            *(float4*)&s_Bs[bi * 128 + bo4] =
                *(const float4*)(W2 + ((size_t)(i0 + bi) * 8 + k) * 128 + bo4);
            __syncthreads();
#pragma unroll
            for (int kk = 0; kk < 8; kk++) {
                const float* ar = s_m1T + (i0 + kk) * 132;
                float4 a0 = *(const float4*)(ar + ty * 4);
                float4 a1 = *(const float4*)(ar + 64 + ty * 4);
                float4 b0 = *(const float4*)(s_Bs + kk * 128 + tx * 4);
                float4 b1v = *(const float4*)(s_Bs + kk * 128 + 64 + tx * 4);
                float a[8] = {a0.x * eas[0], a0.y * eas[1], a0.z * eas[2], a0.w * eas[3],
                              a1.x * eas[4], a1.y * eas[5], a1.z * eas[6], a1.w * eas[7]};
                float b[8] = {b0.x, b0.y, b0.z, b0.w, b1v.x, b1v.y, b1v.z, b1v.w};
#pragma unroll
                for (int m = 0; m < 8; m++)
#pragma unroll
                    for (int n = 0; n < 8; n++) c[m][n] = fmaf(a[m], b[n], c[m][n]);
            }
        }
    }

    // ----- phase 3: swish + scatter-add -----
    float4 b2lo = *(const float4*)(b2 + tx * 4);
    float4 b2hi = *(const float4*)(b2 + 64 + tx * 4);
    const float bb[8] = {b2lo.x, b2lo.y, b2lo.z, b2lo.w, b2hi.x, b2hi.y, b2hi.z, b2hi.w};
#pragma unroll
    for (int m = 0; m < 8; m++) {
        const int row = (m < 4) ? (ty * 4 + m) : (64 + ty * 4 + m - 4);
        const int ge = e0 + row;
        if (ge >= NE) continue;
        const int gd = eidx[NE + ge];
        float* ap = g_agg + (size_t)gd * 128;
#pragma unroll
        for (int n = 0; n < 8; n++) {
            const int col = (n < 4) ? (tx * 4 + n) : (64 + tx * 4 + n - 4);
            atomicAdd(ap + col, swishf(c[m][n] + bb[n]));
        }
    }
}

// ---------------------------------------------------------------------------
// Node kernel: 128 nodes per CTA. Layer3 (K = 259*8) then Layer4 (K = 128*8).
// ---------------------------------------------------------------------------
__global__ void __launch_bounds__(256, 1) k_nodes(
    const float* __restrict__ x, const float* __restrict__ na,
    const float* __restrict__ anf,
    const float* __restrict__ W3, const float* __restrict__ b3,
    const float* __restrict__ W4, const float* __restrict__ b4,
    float* __restrict__ out) {
    extern __shared__ float sm[];
    float* s_na   = sm;            // 1024
    float* s_anfT = sm + 1024;     // 8*132 (rows 3..7 zero)
    float* s_xT   = sm + 2080;     // 128*132   (reused as uT for layer 4)
    float* s_gT   = sm + 18976;    // 128*132
    float* s_Bs   = sm + 35872;    // 1024
    const int tid = threadIdx.x;
    const int n0 = blockIdx.x * 128;
    const int tx = tid & 15, ty = tid >> 4;
    const int bi = tid >> 5, bo4 = (tid & 31) * 4;

    for (int i = tid; i < 1024; i += 256) {
        const int idx = n0 * 8 + i;
        s_na[i] = (idx < NN * 8) ? na[idx] : 0.0f;
    }
    {
        const int r = tid >> 1;
        const int off = (tid & 1) * 64;
        int gn = n0 + r; if (gn >= NN) gn = NN - 1;
#pragma unroll
        for (int j = 0; j < 64; j += 4) {
            float4 v = *(const float4*)(x + (size_t)gn * 128 + off + j);
            s_xT[(off + j + 0) * 132 + r] = v.x;
            s_xT[(off + j + 1) * 132 + r] = v.y;
            s_xT[(off + j + 2) * 132 + r] = v.z;
            s_xT[(off + j + 3) * 132 + r] = v.w;
            float4 g = *(const float4*)(g_agg + (size_t)gn * 128 + off + j);
            s_gT[(off + j + 0) * 132 + r] = g.x;
            s_gT[(off + j + 1) * 132 + r] = g.y;
            s_gT[(off + j + 2) * 132 + r] = g.z;
            s_gT[(off + j + 3) * 132 + r] = g.w;
        }
    }
    if (tid < 128) {
        int gn = n0 + tid;
        const bool v = gn < NN;
        if (!v) gn = 0;
#pragma unroll
        for (int i = 0; i < 8; i++)
            s_anfT[i * 132 + tid] = (i < 3 && v) ? anf[gn * 3 + i] : 0.0f;
    }
    __syncthreads();

    float c[8][8];
#pragma unroll
    for (int m = 0; m < 8; m++)
#pragma unroll
        for (int n = 0; n < 8; n++) c[m][n] = 0.0f;

    // ----- layer 3: K = 259*8 -----
    for (int k = 0; k < 8; k++) {
        float nas[8];
#pragma unroll
        for (int m = 0; m < 8; m++) {
            const int row = (m < 4) ? (ty * 4 + m) : (64 + ty * 4 + m - 4);
            nas[m] = s_na[row * 8 + k];
        }
        for (int blk = 0; blk < 33; blk++) {
            const float* AT = (blk < 16) ? (s_xT + blk * 8 * 132)
                            : (blk < 32) ? (s_gT + (blk - 16) * 8 * 132)
                                         : s_anfT;
            const int gi = blk * 8 + bi;
            __syncthreads();
            float4 bv = make_float4(0.f, 0.f, 0.f, 0.f);
            if (gi < 259)
                bv = *(const float4*)(W3 + ((size_t)gi * 8 + k) * 128 + bo4);
            *(float4*)&s_Bs[bi * 128 + bo4] = bv;
            __syncthreads();
#pragma unroll
            for (int kk = 0; kk < 8; kk++) {
                const float* ar = AT + kk * 132;
                float4 a0 = *(const float4*)(ar + ty * 4);
                float4 a1 = *(const float4*)(ar + 64 + ty * 4);
                float4 b0 = *(const float4*)(s_Bs + kk * 128 + tx * 4);
                float4 b1v = *(const float4*)(s_Bs + kk * 128 + 64 + tx * 4);
                float a[8] = {a0.x * nas[0], a0.y * nas[1], a0.z * nas[2], a0.w * nas[3],
                              a1.x * nas[4], a1.y * nas[5], a1.z * nas[6], a1.w * nas[7]};
                float b[8] = {b0.x, b0.y, b0.z, b0.w, b1v.x, b1v.y, b1v.z, b1v.w};
#pragma unroll
                for (int m = 0; m < 8; m++)
#pragma unroll
                    for (int n = 0; n < 8; n++) c[m][n] = fmaf(a[m], b[n], c[m][n]);
            }
        }
    }

    // u = swish(c + b3) -> uT (overwrite s_xT; all layer-3 reads are done)
    __syncthreads();
    {
        float4 b3lo = *(const float4*)(b3 + tx * 4);
        float4 b3hi = *(const float4*)(b3 + 64 + tx * 4);
        const float bb[8] = {b3lo.x, b3lo.y, b3lo.z, b3lo.w, b3hi.x, b3hi.y, b3hi.z, b3hi.w};
#pragma unroll
        for (int m = 0; m < 8; m++) {
            const int row = (m < 4) ? (ty * 4 + m) : (64 + ty * 4 + m - 4);
#pragma unroll
            for (int n = 0; n < 8; n++) {
                const int col = (n < 4) ? (tx * 4 + n) : (64 + tx * 4 + n - 4);
                s_xT[col * 132 + row] = swishf(c[m][n] + bb[n]);
            }
        }
    }
    __syncthreads();

    // ----- layer 4: K = 128*8 -----
#pragma unroll
    for (int m = 0; m < 8; m++)
#pragma unroll
        for (int n = 0; n < 8; n++) c[m][n] = 0.0f;

    for (int k = 0; k < 8; k++) {
        float nas[8];
#pragma unroll
        for (int m = 0; m < 8; m++) {
            const int row = (m < 4) ? (ty * 4 + m) : (64 + ty * 4 + m - 4);
            nas[m] = s_na[row * 8 + k];
        }
        for (int i0 = 0; i0 < 128; i0 += 8) {
            __syncthreads();
            *(float4*)&s_Bs[bi * 128 + bo4] =
                *(const float4*)(W4 + ((size_t)(i0 + bi) * 8 + k) * 128 + bo4);
            __syncthreads();
#pragma unroll
            for (int kk = 0; kk < 8; kk++) {
                const float* ar = s_xT + (i0 + kk) * 132;
                float4 a0 = *(const float4*)(ar + ty * 4);
                float4 a1 = *(const float4*)(ar + 64 + ty * 4);
                float4 b0 = *(const float4*)(s_Bs + kk * 128 + tx * 4);
                float4 b1v = *(const float4*)(s_Bs + kk * 128 + 64 + tx * 4);
                float a[8] = {a0.x * nas[0], a0.y * nas[1], a0.z * nas[2], a0.w * nas[3],
                              a1.x * nas[4], a1.y * nas[5], a1.z * nas[6], a1.w * nas[7]};
                float b[8] = {b0.x, b0.y, b0.z, b0.w, b1v.x, b1v.y, b1v.z, b1v.w};
#pragma unroll
                for (int m = 0; m < 8; m++)
#pragma unroll
                    for (int n = 0; n < 8; n++) c[m][n] = fmaf(a[m], b[n], c[m][n]);
            }
        }
    }

    // out = c + b4
    {
        float4 b4lo = *(const float4*)(b4 + tx * 4);
        float4 b4hi = *(const float4*)(b4 + 64 + tx * 4);
#pragma unroll
        for (int m = 0; m < 8; m++) {
            const int row = (m < 4) ? (ty * 4 + m) : (64 + ty * 4 + m - 4);
            const int gn = n0 + row;
            if (gn >= NN) continue;
            float4 v0 = {c[m][0] + b4lo.x, c[m][1] + b4lo.y, c[m][2] + b4lo.z, c[m][3] + b4lo.w};
            float4 v1 = {c[m][4] + b4hi.x, c[m][5] + b4hi.y, c[m][6] + b4hi.z, c[m][7] + b4hi.w};
            *(float4*)(out + (size_t)gn * 128 + tx * 4) = v0;
            *(float4*)(out + (size_t)gn * 128 + 64 + tx * 4) = v1;
        }
    }
}

extern "C" void kernel_launch(void* const* d_in, const int* in_sizes, int n_in,
                              void* d_out, int out_size) {
    const float *x = nullptr, *ea = nullptr, *na = nullptr, *amf = nullptr, *anf = nullptr;
    const float *W1 = nullptr, *b1 = nullptr, *W2 = nullptr, *b2 = nullptr;
    const float *W3 = nullptr, *b3 = nullptr, *W4 = nullptr, *b4 = nullptr;
    const int* eidx = nullptr;
    for (int i = 0; i < n_in; i++) {
        switch (in_sizes[i]) {
            case 6400000: x   = (const float*)d_in[i]; break;
            case 1000000: eidx = (const int*)d_in[i]; break;
            case 4000000: ea  = (const float*)d_in[i]; break;
            case 400000:  na  = (const float*)d_in[i]; break;
            case 1500000: amf = (const float*)d_in[i]; break;
            case 150000:  anf = (const float*)d_in[i]; break;
            case 265216:  if (!W1) W1 = (const float*)d_in[i]; else W3 = (const float*)d_in[i]; break;
            case 131072:  if (!W2) W2 = (const float*)d_in[i]; else W4 = (const float*)d_in[i]; break;
            case 128:
                if (!b1) b1 = (const float*)d_in[i];
                else if (!b2) b2 = (const float*)d_in[i];
                else if (!b3) b3 = (const float*)d_in[i];
                else b4 = (const float*)d_in[i];
                break;
            default: break;  // batch (50000 int64) unused
        }
    }

    cudaFuncSetAttribute(k_edges, cudaFuncAttributeMaxDynamicSharedMemorySize, 88064);
    cudaFuncSetAttribute(k_nodes, cudaFuncAttributeMaxDynamicSharedMemorySize, 147584);

    k_zero_agg<<<12500, 512>>>();
    dim3 gp(391, 8, 2);
    k_precompute<<<gp, 256>>>(x, W1);
    k_edges<<<3907, 256, 88064>>>(eidx, ea, amf, W1, b1, W2, b2);
    k_nodes<<<391, 256, 147584>>>(x, na, anf, W3, b3, W4, b4, (float*)d_out);
}